// round 15
// baseline (speedup 1.0000x reference)
#include <cuda_runtime.h>
#include <math.h>

#define NB 2
#define NN 1024
#define NC 32
#define BN_EPS 1e-3f
#define CAPX 4160            // 65 base segs x <=64 crossings
#define CAPF (CAPX + 65)
#define LUT_BIAS 6592        // (bits>>17) of d=2^-24
#define LUT_N 4160           // covers d up to ~2^41
#define SCAP 102             // segments cached in smem by main kernel

// ---- device-global tables (allocation-free scratch) ----
__device__ float  gFineHi[CAPF];        // fine-seg upper bounds (global monotone)
__device__ float4 gRn[CAPF * 5];        // per fine seg: rn0[0..8], rn1[0..8], pad
__device__ int    gNFine;
__device__ uint2  gLutRaw[LUT_N / 4];   // 8-byte aligned backing for ushort LUT

// =====================================================================
// prep_all: ONE launch, 65 CTAs (one per base segment t1), 64 threads.
// Each thread k walks the incremental (S0,S1) chain across all 65 base
// segments locally -> CTA knows all crossing counts (prefix offsets are
// local), its own segment's S row, its crossings. Emits rn rows, fine
// boundaries, and its disjoint slice of the bucket LUT.
// =====================================================================
__global__ __launch_bounds__(64)
void prep_all_kernel(const float* __restrict__ W1, const float* __restrict__ b1,
                     const float* __restrict__ g1, const float* __restrict__ be1,
                     const float* __restrict__ m1, const float* __restrict__ v1,
                     const float* __restrict__ W2, const float* __restrict__ b2,
                     const float* __restrict__ g2, const float* __restrict__ be2,
                     const float* __restrict__ m2, const float* __restrict__ v2,
                     const float* __restrict__ W3, const float* __restrict__ b3)
{
    __shared__ float sTauU[64], sTau[64];
    __shared__ float sDs[64], sDc[64], sSlB[64], sCoB[64], sBB1[64], sBB2[64];
    __shared__ int   sOn0[64], sOrder[64];
    __shared__ int   sCntW[2][65];
    __shared__ float sHasD[64];
    __shared__ int   sHasF[64];
    __shared__ float sCr[64];
    __shared__ float sB3p[9];
    __shared__ float sRed[2][18];

    unsigned short* gLut = (unsigned short*)gLutRaw;

    const int t1   = blockIdx.x;     // 0..64
    const int f    = threadIdx.x;    // 0..63
    const int warp = f >> 5, lane = f & 31;
    const float INFv = __int_as_float(0x7f800000);

    // ---- stage A: per-feature knots + folded BN ----
    const float w1 = __ldg(&W1[f]), bb = __ldg(&b1[f]);
    const float a1 = __ldg(&g1[f]) * rsqrtf(__ldg(&v1[f]) + BN_EPS);
    const float a2 = __ldg(&g2[f]) * rsqrtf(__ldg(&v2[f]) + BN_EPS);
    sBB1[f] = __ldg(&be1[f]) - __ldg(&m1[f]) * a1;
    sBB2[f] = __ldg(&be2[f]) - __ldg(&m2[f]) * a2;
    const float slope = a1 * w1, cons = a1 * bb;
    float tau, ds, dc; int on0;
    if (w1 > 0.f)      { tau = -bb / w1; ds =  slope; dc =  cons; on0 = 0; }
    else if (w1 < 0.f) { tau = -bb / w1; ds = -slope; dc = -cons; on0 = 1; }
    else { tau = INFv; ds = 0.f; dc = 0.f; on0 = (bb > 0.f) ? 1 : 0; }
    sTauU[f] = tau; sDs[f] = ds; sDc[f] = dc; sSlB[f] = slope; sCoB[f] = cons; sOn0[f] = on0;
    float w3p[9];
    #pragma unroll
    for (int o = 0; o < 9; o++) w3p[o] = __ldg(&W3[f * 9 + o]) * a2;
    __syncthreads();

    // stable rank sort of taus
    int rank = 0;
    #pragma unroll
    for (int g = 0; g < 64; g++) {
        const float tg = sTauU[g];
        rank += (tg < tau) || (tg == tau && g < f);
    }
    sOrder[rank] = f;
    sTau[rank]   = tau;
    __syncthreads();

    if (f < 9) {                                     // b3p = b3 + W3^T*BB2
        float s = __ldg(&b3[f]);
        #pragma unroll
        for (int g = 0; g < 64; g++) s += __ldg(&W3[g * 9 + f]) * sBB2[g];
        sB3p[f] = s;
    }

    // ---- incremental S walk (unit k = f) over all base segments ----
    const int k = f;
    float S0 = __ldg(&b2[k]), S1 = 0.f;
    #pragma unroll 4
    for (int g = 0; g < 64; g++) {
        const float w2 = __ldg(&W2[g * 64 + k]);
        float add0 = sBB1[g], add1 = 0.f;
        if (sOn0[g]) { add0 += sCoB[g]; add1 += sSlB[g]; }
        S0 = fmaf(w2, add0, S0);
        S1 = fmaf(w2, add1, S1);
    }
    float mS0 = 0.f, mS1 = 0.f, myD = 0.f;
    int myHas = 0;
    for (int t = 0; t <= 64; t++) {
        const float lo = (t == 0)  ? -INFv : sTau[t - 1];
        const float hi = (t == 64) ?  INFv : sTau[t];
        float dstar = 0.f; bool has = false;
        if (S1 != 0.f) { dstar = -S0 / S1; has = (dstar > lo && dstar < hi); }
        const unsigned mb = __ballot_sync(0xffffffffu, has);
        if (lane == 0) sCntW[warp][t] = __popc(mb);
        if (t == t1) { mS0 = S0; mS1 = S1; myHas = has ? 1 : 0; myD = dstar; }
        if (t < 64) {
            const int ff = sOrder[t];
            const float w2 = __ldg(&W2[ff * 64 + k]);
            S0 = fmaf(w2, sDc[ff], S0);
            S1 = fmaf(w2, sDs[ff], S1);
        }
    }
    sHasD[f] = myD;
    sHasF[f] = myHas;
    __syncthreads();

    // counts / prefix (local, every thread identical)
    int cb = 0, tot = 0, c = 0;
    for (int t = 0; t <= 64; t++) {
        const int ct = sCntW[0][t] + sCntW[1][t];
        if (t < t1) cb += ct;
        if (t == t1) c = ct;
        tot += ct;
    }
    if (t1 == 0 && f == 0) { gNFine = tot + 65; gLut[0] = 0; }

    // sort own crossings (rank sort, ties by unit index)
    if (myHas) {
        int rk = 0;
        for (int i2 = 0; i2 < 64; i2++) {
            if (sHasF[i2]) {
                const float vi = sHasD[i2];
                rk += (vi < myD) || (vi == myD && i2 < f);
            }
        }
        sCr[rk] = myD;
    }
    __syncthreads();

    const float lo0 = (t1 == 0)  ? -INFv : sTau[t1 - 1];
    const float hi0 = (t1 == 64) ?  INFv : sTau[t1];
    const float dlo1 = __int_as_float((1 + LUT_BIAS) << 17);

    for (int pos = 0; pos <= c; pos++) {
        const float lo = (pos == 0) ? lo0 : sCr[pos - 1];
        const float hi = (pos == c) ? hi0 : sCr[pos];
        const bool loinf = isinf(lo), hiinf = isinf(hi);
        float mid;
        if (loinf && hiinf) mid = 1.f;
        else if (loinf)     mid = hi - 1.f;
        else if (hiinf)     mid = lo + 1.f;
        else                mid = 0.5f * (lo + hi);

        const bool act = fmaf(mid, mS1, mS0) > 0.f;
        float r0[9], r1[9];
        #pragma unroll
        for (int o = 0; o < 9; o++) {
            r0[o] = act ? mS0 * w3p[o] : 0.f;
            r1[o] = act ? mS1 * w3p[o] : 0.f;
        }
        #pragma unroll
        for (int off = 16; off; off >>= 1) {
            #pragma unroll
            for (int o = 0; o < 9; o++) {
                r0[o] += __shfl_xor_sync(0xffffffffu, r0[o], off);
                r1[o] += __shfl_xor_sync(0xffffffffu, r1[o], off);
            }
        }
        if (lane == 0) {
            #pragma unroll
            for (int o = 0; o < 9; o++) {
                sRed[warp][o]     = r0[o];
                sRed[warp][9 + o] = r1[o];
            }
        }
        __syncthreads();
        const int fi = cb + t1 + pos;
        if (f == 0) {
            float rn0[9], rn1[9];
            #pragma unroll
            for (int o = 0; o < 9; o++) {
                rn0[o] = sB3p[o] + sRed[0][o] + sRed[1][o];
                rn1[o] = sRed[0][9 + o] + sRed[1][9 + o];
            }
            gRn[fi * 5 + 0] = make_float4(rn0[0], rn0[1], rn0[2], rn0[3]);
            gRn[fi * 5 + 1] = make_float4(rn0[4], rn0[5], rn0[6], rn0[7]);
            gRn[fi * 5 + 2] = make_float4(rn0[8], rn1[0], rn1[1], rn1[2]);
            gRn[fi * 5 + 3] = make_float4(rn1[3], rn1[4], rn1[5], rn1[6]);
            gRn[fi * 5 + 4] = make_float4(rn1[7], rn1[8], 0.f, 0.f);
            gFineHi[fi] = hi;
        }
        // LUT slice: buckets i with d_lo(i) in (lo, hi]  (disjoint across segs)
        int imin, imax;
        if (lo < dlo1) imin = 1;
        else {
            int ib = (__float_as_int(lo) >> 17) - LUT_BIAS;
            imin = ib + 1;
        }
        if (hiinf) imax = LUT_N - 1;
        else if (hi < dlo1) imax = 0;
        else {
            int ib = (__float_as_int(hi) >> 17) - LUT_BIAS;
            imax = ib < LUT_N - 1 ? ib : LUT_N - 1;
        }
        for (int i2 = imin + f; i2 <= imax; i2 += 64)
            gLut[i2] = (unsigned short)fi;
        __syncthreads();
    }
}

// =====================================================================
// Main kernel: one CTA (128 thr) per output row (b,i).
// Hot tables (LUT + first SCAP segments) staged in shared.
// =====================================================================
__global__ __launch_bounds__(128)
void e2conv_kernel(const float* __restrict__ r, const float* __restrict__ x,
                   const float* __restrict__ a, const float* __restrict__ si,
                   float* __restrict__ out)
{
    __shared__ float2   sJA[NN + 4];           // (j as float, aw)   8224 B
    __shared__ unsigned sMask[32];
    __shared__ int      sOff[33];
    __shared__ float    sPartR[4][96], sPartI[4][96];
    __shared__ float    sSi[3];
    __shared__ int      sNF;
    __shared__ uint2    sLutRaw[LUT_N / 4];    // 8320 B, 8-byte aligned
    __shared__ float    sHi[SCAP];             // 408 B
    __shared__ float4   sRn[SCAP * 5];         // 8160 B

    unsigned short* sLut = (unsigned short*)sLutRaw;

    const int tid  = threadIdx.x;
    const int warp = tid >> 5;
    const int lane = tid & 31;

    if (tid == 0) sNF = gNFine;
    if (tid < 3) sSi[tid] = si[tid];

    const int bi = blockIdx.x;
    const int b  = bi >> 10;
    const int i  = bi & (NN - 1);
    const float2 ri = ((const float2*)r)[b * NN + i];
    const float* __restrict__ arow = a + (size_t)(b * NN + i) * NN;

    // ---- phase 1: ballots ----
    float av8[8];
    #pragma unroll
    for (int k = 0; k < 8; k++) {
        const int chunk = warp * 8 + k;
        const int jl = chunk * 32 + lane;
        const float av = arow[jl];
        av8[k] = av;
        const unsigned msk = __ballot_sync(0xffffffffu, (av != 0.f) && (jl != i));
        if (lane == 0) sMask[chunk] = msk;
    }
    __syncthreads();
    // warp0: prefix scan; warps 1-3: copy LUT to shared
    if (warp == 0) {
        int ex = __popc(sMask[lane]);
        #pragma unroll
        for (int off = 1; off < 32; off <<= 1) {
            const int v = __shfl_up_sync(0xffffffffu, ex, off);
            if (lane >= off) ex += v;
        }
        sOff[lane + 1] = ex;
        if (lane == 0) sOff[0] = 0;
    } else {
        for (int t = tid - 32; t < LUT_N / 4; t += 96)
            sLutRaw[t] = __ldg(&gLutRaw[t]);
    }
    __syncthreads();
    const int cnt = sOff[32];
    const int nF  = sNF;
    const int nCache = nF < SCAP ? nF : SCAP;
    #pragma unroll
    for (int k = 0; k < 8; k++) {
        const int chunk = warp * 8 + k;
        const unsigned msk = sMask[chunk];
        if (msk & (1u << lane)) {
            const int pos = sOff[chunk] + __popc(msk & ((1u << lane) - 1u));
            sJA[pos] = make_float2((float)(chunk * 32 + lane), av8[k]);
        }
    }
    // copy segment tables (independent of scatter)
    for (int t = tid; t < nCache * 5; t += 128) sRn[t] = __ldg(&gRn[t]);
    for (int t = tid; t < nCache;     t += 128) sHi[t] = __ldg(&gFineHi[t]);
    __syncthreads();
    const int cntPad = (cnt + 3) & ~3;
    if (cnt > 0 && tid < cntPad - cnt) sJA[cnt + tid] = make_float2(sJA[0].x, 0.f);
    __syncthreads();

    float accR[3] = {0.f, 0.f, 0.f};
    float accI[3] = {0.f, 0.f, 0.f};

    // ---- main loop: batches of 4 pairs per warp ----
    for (int base = warp * 4; base < cntPad; base += 16) {
        float c1a[4], s1a[4], dv[4];
        float xmv[4][3];
        int   sg[4];

        #pragma unroll
        for (int p = 0; p < 4; p++) {
            const float2 ja = sJA[base + p];
            const int jv = (int)ja.x;
            const float aw = ja.y;
            const float2 rj = __ldg(&((const float2*)r)[b * NN + jv]);
            const float dx = ri.x - rj.x;
            const float dy = ri.y - rj.y;
            const float dd = fmaf(dx, dx, dy * dy);
            const float inv = rsqrtf(fmaxf(dd, 1e-30f));
            const float d  = dd * inv;
            dv[p]  = d;
            c1a[p] = dx * inv;
            s1a[p] = dy * inv;
            const float* __restrict__ xj = x + ((size_t)(b * NN + jv) * 3) * NC + lane;
            xmv[p][0] = __ldg(xj)          * aw;
            xmv[p][1] = __ldg(xj + NC)     * aw;
            xmv[p][2] = __ldg(xj + 2 * NC) * aw;

            // bucket LUT (smem) + forward walk (smem/global select)
            int idx = (__float_as_int(d) >> 17) - LUT_BIAS;
            idx = idx < 0 ? 0 : (idx > LUT_N - 1 ? LUT_N - 1 : idx);
            int seg = sLut[idx];
            for (;;) {
                const float h = (seg < nCache) ? sHi[seg] : __ldg(&gFineHi[seg]);
                if (h >= d) break;
                seg++;
            }
            sg[p] = seg;
        }

        #pragma unroll
        for (int p = 0; p < 4; p++) {
            const float d = dv[p];
            const int seg = sg[p];
            float4 q0, q1, q2, q3, q4;
            if (seg < nCache) {
                const float4* tp = &sRn[seg * 5];
                q0 = tp[0]; q1 = tp[1]; q2 = tp[2]; q3 = tp[3]; q4 = tp[4];
            } else {
                const float4* tp = &gRn[seg * 5];
                q0 = __ldg(tp + 0); q1 = __ldg(tp + 1); q2 = __ldg(tp + 2);
                q3 = __ldg(tp + 3); q4 = __ldg(tp + 4);
            }
            float w[9];
            w[0] = fmaf(d, q2.y, q0.x);
            w[1] = fmaf(d, q2.z, q0.y);
            w[2] = fmaf(d, q2.w, q0.z);
            w[3] = fmaf(d, q3.x, q0.w);
            w[4] = fmaf(d, q3.y, q1.x);
            w[5] = fmaf(d, q3.z, q1.y);
            w[6] = fmaf(d, q3.w, q1.z);
            w[7] = fmaf(d, q4.x, q1.w);
            w[8] = fmaf(d, q4.y, q2.x);

            const float c1v = c1a[p], s1v = s1a[p];
            const float c2v = fmaf(2.f * c1v, c1v, -1.f);
            const float s2v = 2.f * s1v * c1v;
            const float cK[5] = { c2v,  c1v, 1.f, c1v, c2v };
            const float sK[5] = {-s2v, -s1v, 0.f, s1v, s2v };
            #pragma unroll
            for (int m = 0; m < 3; m++) {
                #pragma unroll
                for (int n = 0; n < 3; n++) {
                    const int k = n - m + 2;
                    const float u = w[m * 3 + n] * xmv[p][m];
                    accR[n] = fmaf(cK[k], u, accR[n]);
                    accI[n] = fmaf(sK[k], u, accI[n]);
                }
            }
        }
    }

    // ---- deterministic cross-warp reduction ----
    #pragma unroll
    for (int n = 0; n < 3; n++) {
        sPartR[warp][n * NC + lane] = accR[n];
        sPartI[warp][n * NC + lane] = accI[n];
    }
    __syncthreads();

    if (tid < 96) {
        const int n = tid / NC;
        const int c = tid % NC;
        const float sr  = sPartR[0][tid] + sPartR[1][tid] + sPartR[2][tid] + sPartR[3][tid];
        const float sim = sPartI[0][tid] + sPartI[1][tid] + sPartI[2][tid] + sPartI[3][tid];
        const float xs = x[((size_t)(b * NN + i) * 3 + n) * NC + c];
        const size_t baseR = ((((size_t)0 * NB + b) * NN + i) * 3 + n) * NC + c;
        const size_t baseI = ((((size_t)1 * NB + b) * NN + i) * 3 + n) * NC + c;
        out[baseR] = fmaf(sSi[n], xs, sr);   // self term: W_self = diag(si)
        out[baseI] = sim;
    }
}

extern "C" void kernel_launch(void* const* d_in, const int* in_sizes, int n_in,
                              void* d_out, int out_size) {
    const float* r   = (const float*)d_in[0];
    const float* x   = (const float*)d_in[1];
    const float* a   = (const float*)d_in[2];
    const float* W1  = (const float*)d_in[3];
    const float* b1  = (const float*)d_in[4];
    const float* g1  = (const float*)d_in[5];
    const float* be1 = (const float*)d_in[6];
    const float* m1  = (const float*)d_in[7];
    const float* v1  = (const float*)d_in[8];
    const float* W2  = (const float*)d_in[9];
    const float* b2  = (const float*)d_in[10];
    const float* g2  = (const float*)d_in[11];
    const float* be2 = (const float*)d_in[12];
    const float* m2  = (const float*)d_in[13];
    const float* v2  = (const float*)d_in[14];
    const float* W3  = (const float*)d_in[15];
    const float* b3  = (const float*)d_in[16];
    const float* si  = (const float*)d_in[17];
    float* out = (float*)d_out;

    prep_all_kernel<<<65, 64>>>(W1, b1, g1, be1, m1, v1, W2, b2,
                                g2, be2, m2, v2, W3, b3);
    e2conv_kernel<<<NB * NN, 128>>>(r, x, a, si, out);
}

// round 17
// speedup vs baseline: 1.5538x; 1.5538x over previous
#include <cuda_runtime.h>
#include <math.h>

#define NB 2
#define NN 1024
#define NC 32
#define BN_EPS 1e-3f
#define CAPX 4160            // 65 base segs x <=64 crossings
#define CAPF (CAPX + 65)
#define LUT_BIAS 6592        // (bits>>17) of d=2^-24
#define LUT_N 4160           // covers d up to ~2^41

// ---- device-global scratch (allocation-free) ----
__device__ float2 gS[65 * 64];          // [t1][k] base-segment (S0,S1)
__device__ float  gCrossByT1[65 * 64];  // sorted crossings, fixed stride per t1
__device__ int    gCnt[65];             // crossings per base segment
__device__ float  gFineHi[CAPF];        // fine-segment upper boundaries (global monotone)
__device__ float4 gRn[CAPF * 5];        // per fine seg: rn0[0..8], rn1[0..8], pad
__device__ int    gNFine;
__device__ unsigned short gLut[LUT_N];

// =====================================================================
// prepB: one CTA per base segment t1. Computes S-row directly (closed-form
// active set), finds+sorts this segment's layer-2 zero crossings.
// =====================================================================
__global__ __launch_bounds__(64)
void prepB_kernel(const float* __restrict__ W1, const float* __restrict__ b1,
                  const float* __restrict__ g1, const float* __restrict__ be1,
                  const float* __restrict__ m1, const float* __restrict__ v1,
                  const float* __restrict__ W2, const float* __restrict__ b2)
{
    __shared__ float sTauU[64], sTau[64], sDs[64], sDc[64], sSlB[64], sCoB[64], sBB1[64];
    __shared__ int   sOn0[64], sRank[64];
    __shared__ float sCr[64];
    __shared__ int   sWcnt[2];

    const int t1   = blockIdx.x;     // 0..64
    const int f    = threadIdx.x;    // 0..63
    const int warp = f >> 5, lane = f & 31;
    const float INFv = __int_as_float(0x7f800000);

    const float w1 = __ldg(&W1[f]), bb = __ldg(&b1[f]);
    const float a1 = __ldg(&g1[f]) * rsqrtf(__ldg(&v1[f]) + BN_EPS);
    sBB1[f] = __ldg(&be1[f]) - __ldg(&m1[f]) * a1;
    const float slope = a1 * w1, cons = a1 * bb;
    float tau, ds, dc; int on0;
    if (w1 > 0.f)      { tau = -bb / w1; ds =  slope; dc =  cons; on0 = 0; }
    else if (w1 < 0.f) { tau = -bb / w1; ds = -slope; dc = -cons; on0 = 1; }
    else { tau = INFv; ds = 0.f; dc = 0.f; on0 = (bb > 0.f) ? 1 : 0; }
    sTauU[f] = tau; sDs[f] = ds; sDc[f] = dc; sSlB[f] = slope; sCoB[f] = cons; sOn0[f] = on0;
    __syncthreads();

    int rank = 0;
    #pragma unroll
    for (int g = 0; g < 64; g++) {
        const float tg = sTauU[g];
        rank += (tg < tau) || (tg == tau && g < f);
    }
    sRank[f] = rank;
    sTau[rank] = tau;
    __syncthreads();

    const int k = f;
    float S0 = __ldg(&b2[k]), S1 = 0.f;
    #pragma unroll
    for (int g = 0; g < 64; g++) {
        const float w2 = __ldg(&W2[g * 64 + k]);
        float add0 = sBB1[g], add1 = 0.f;
        if (sOn0[g])      { add0 += sCoB[g]; add1 += sSlB[g]; }
        if (t1 > sRank[g]) { add0 += sDc[g]; add1 += sDs[g]; }
        S0 = fmaf(w2, add0, S0);
        S1 = fmaf(w2, add1, S1);
    }
    gS[t1 * 64 + k] = make_float2(S0, S1);

    const float lo = (t1 == 0)  ? -INFv : sTau[t1 - 1];
    const float hi = (t1 == 64) ?  INFv : sTau[t1];
    float dstar = 0.f; bool has = false;
    if (S1 != 0.f) { dstar = -S0 / S1; has = (dstar > lo && dstar < hi); }
    const unsigned mball = __ballot_sync(0xffffffffu, has);
    if (lane == 0) sWcnt[warp] = __popc(mball);
    __syncthreads();
    const int base = (warp == 1) ? sWcnt[0] : 0;
    if (has) sCr[base + __popc(mball & ((1u << lane) - 1u))] = dstar;
    __syncthreads();
    const int c = sWcnt[0] + sWcnt[1];
    if (f < c) {
        const float v = sCr[f];
        int rk = 0;
        for (int i = 0; i < c; i++) {
            const float vi = sCr[i];
            rk += (vi < v) || (vi == v && i < f);
        }
        gCrossByT1[t1 * 64 + rk] = v;
    }
    if (f == 0) gCnt[t1] = c;
}

// =====================================================================
// prepD: one CTA per base segment t1. Emits fine-segment boundaries and
// rn0/rn1 coefficient rows.
// =====================================================================
__global__ __launch_bounds__(64)
void prepD_kernel(const float* __restrict__ W1, const float* __restrict__ b1,
                  const float* __restrict__ g2, const float* __restrict__ be2,
                  const float* __restrict__ m2, const float* __restrict__ v2,
                  const float* __restrict__ W3, const float* __restrict__ b3)
{
    __shared__ float sTauU[64], sTau[64], sBB2[64], sB3p[9];
    __shared__ float sCr[64];
    __shared__ int   sCnt[65];
    __shared__ float sRed[2][18];

    const int t1   = blockIdx.x;
    const int f    = threadIdx.x;
    const int warp = f >> 5, lane = f & 31;
    const float INFv = __int_as_float(0x7f800000);

    const float w1 = __ldg(&W1[f]), bb = __ldg(&b1[f]);
    const float tau = (w1 != 0.f) ? (-bb / w1) : INFv;
    sTauU[f] = tau;
    const float a2 = __ldg(&g2[f]) * rsqrtf(__ldg(&v2[f]) + BN_EPS);
    sBB2[f] = __ldg(&be2[f]) - __ldg(&m2[f]) * a2;
    float w3p[9];
    #pragma unroll
    for (int o = 0; o < 9; o++) w3p[o] = __ldg(&W3[f * 9 + o]) * a2;
    if (f < 64) sCnt[f] = gCnt[f];
    if (f == 0) sCnt[64] = gCnt[64];
    __syncthreads();
    int rank = 0;
    #pragma unroll
    for (int g = 0; g < 64; g++) {
        const float tg = sTauU[g];
        rank += (tg < tau) || (tg == tau && g < f);
    }
    sTau[rank] = tau;
    __syncthreads();

    if (f < 9) {
        float s = __ldg(&b3[f]);
        #pragma unroll
        for (int g = 0; g < 64; g++) s += __ldg(&W3[g * 9 + f]) * sBB2[g];
        sB3p[f] = s;
    }

    int cb = 0;
    for (int t = 0; t < t1; t++) cb += sCnt[t];
    const int c = sCnt[t1];
    if (f < c) sCr[f] = gCrossByT1[t1 * 64 + f];
    if (t1 == 0 && f == 0) {
        int tot = 0;
        #pragma unroll
        for (int t = 0; t <= 64; t++) tot += sCnt[t];
        gNFine = tot + 65;
    }
    const float2 sv = gS[t1 * 64 + f];
    __syncthreads();

    const float lo0 = (t1 == 0)  ? -INFv : sTau[t1 - 1];
    const float hi0 = (t1 == 64) ?  INFv : sTau[t1];

    for (int pos = 0; pos <= c; pos++) {
        const float lo = (pos == 0) ? lo0 : sCr[pos - 1];
        const float hi = (pos == c) ? hi0 : sCr[pos];
        const bool loinf = isinf(lo), hiinf = isinf(hi);
        float mid;
        if (loinf && hiinf) mid = 1.f;
        else if (loinf)     mid = hi - 1.f;
        else if (hiinf)     mid = lo + 1.f;
        else                mid = 0.5f * (lo + hi);

        const bool act = fmaf(mid, sv.y, sv.x) > 0.f;
        float r0[9], r1[9];
        #pragma unroll
        for (int o = 0; o < 9; o++) {
            r0[o] = act ? sv.x * w3p[o] : 0.f;
            r1[o] = act ? sv.y * w3p[o] : 0.f;
        }
        #pragma unroll
        for (int off = 16; off; off >>= 1) {
            #pragma unroll
            for (int o = 0; o < 9; o++) {
                r0[o] += __shfl_xor_sync(0xffffffffu, r0[o], off);
                r1[o] += __shfl_xor_sync(0xffffffffu, r1[o], off);
            }
        }
        if (lane == 0) {
            #pragma unroll
            for (int o = 0; o < 9; o++) {
                sRed[warp][o]     = r0[o];
                sRed[warp][9 + o] = r1[o];
            }
        }
        __syncthreads();
        if (f == 0) {
            const int fi = cb + t1 + pos;
            float rn0[9], rn1[9];
            #pragma unroll
            for (int o = 0; o < 9; o++) {
                rn0[o] = sB3p[o] + sRed[0][o] + sRed[1][o];
                rn1[o] = sRed[0][9 + o] + sRed[1][9 + o];
            }
            gRn[fi * 5 + 0] = make_float4(rn0[0], rn0[1], rn0[2], rn0[3]);
            gRn[fi * 5 + 1] = make_float4(rn0[4], rn0[5], rn0[6], rn0[7]);
            gRn[fi * 5 + 2] = make_float4(rn0[8], rn1[0], rn1[1], rn1[2]);
            gRn[fi * 5 + 3] = make_float4(rn1[3], rn1[4], rn1[5], rn1[6]);
            gRn[fi * 5 + 4] = make_float4(rn1[7], rn1[8], 0.f, 0.f);
            gFineHi[fi] = hi;
        }
        __syncthreads();
    }
}

// =====================================================================
// prep2: bucket LUT over float bits of d (lower bound per bucket).
// =====================================================================
__global__ void prep2_kernel()
{
    const int i = blockIdx.x * blockDim.x + threadIdx.x;
    if (i >= LUT_N) return;
    unsigned short v = 0;
    if (i > 0) {
        const int nF = gNFine;
        const float dlo = __int_as_float((i + LUT_BIAS) << 17);
        int pos = 0;
        #pragma unroll
        for (int s = 4096; s; s >>= 1) {
            const int np = pos + s;
            if (np <= nF && __ldg(&gFineHi[np - 1]) < dlo) pos = np;
        }
        v = (unsigned short)pos;
    }
    gLut[i] = v;
}

// =====================================================================
// Main kernel: R13 base + ONE cached segment (96B) in shared.
// Fast path: lo < d <= hi -> coefficients via LDS broadcast, zero LDGs.
// =====================================================================
__global__ __launch_bounds__(128)
void e2conv_kernel(const float* __restrict__ r, const float* __restrict__ x,
                   const float* __restrict__ a, const float* __restrict__ si,
                   float* __restrict__ out)
{
    __shared__ float2   sJA[NN + 4];     // (j as float, aw)
    __shared__ unsigned sMask[32];
    __shared__ int      sOff[33];
    __shared__ float    sPartR[4][96], sPartI[4][96];
    __shared__ float    sSi[3];
    __shared__ float4   sSegRn[5];       // cached segment coefficients
    __shared__ float    sSegLo, sSegHi;  // cached segment bounds

    const int tid  = threadIdx.x;
    const int warp = tid >> 5;
    const int lane = tid & 31;

    if (tid < 3) sSi[tid] = si[tid];

    const int bi = blockIdx.x;
    const int b  = bi >> 10;
    const int i  = bi & (NN - 1);
    const float2 ri = ((const float2*)r)[b * NN + i];
    const float* __restrict__ arow = a + (size_t)(b * NN + i) * NN;

    // ---- deterministic compaction of active neighbors ----
    float av8[8];
    #pragma unroll
    for (int k = 0; k < 8; k++) {
        const int chunk = warp * 8 + k;
        const int jl = chunk * 32 + lane;
        const float av = arow[jl];
        av8[k] = av;
        const unsigned msk = __ballot_sync(0xffffffffu, (av != 0.f) && (jl != i));
        if (lane == 0) sMask[chunk] = msk;
    }
    __syncthreads();
    if (warp == 0) {
        int ex = __popc(sMask[lane]);
        #pragma unroll
        for (int off = 1; off < 32; off <<= 1) {
            const int v = __shfl_up_sync(0xffffffffu, ex, off);
            if (lane >= off) ex += v;
        }
        sOff[lane + 1] = ex;
        if (lane == 0) sOff[0] = 0;
    }
    __syncthreads();
    const int cnt = sOff[32];
    #pragma unroll
    for (int k = 0; k < 8; k++) {
        const int chunk = warp * 8 + k;
        const unsigned msk = sMask[chunk];
        if (msk & (1u << lane)) {
            const int pos = sOff[chunk] + __popc(msk & ((1u << lane) - 1u));
            sJA[pos] = make_float2((float)(chunk * 32 + lane), av8[k]);
        }
    }
    __syncthreads();
    const int cntPad = (cnt + 3) & ~3;
    if (cnt > 0 && tid < cntPad - cnt) sJA[cnt + tid] = make_float2(sJA[0].x, 0.f);

    // ---- cache the segment of the first pair's d (threads 0..7, identical seg) ----
    if (cnt > 0 && tid < 8) {
        const int jv0 = (int)sJA[0].x;
        const float2 rj0 = __ldg(&((const float2*)r)[b * NN + jv0]);
        const float dx0 = ri.x - rj0.x, dy0 = ri.y - rj0.y;
        const float dd0 = fmaf(dx0, dx0, dy0 * dy0);
        const float d0 = dd0 * rsqrtf(fmaxf(dd0, 1e-30f));
        int idx = (__float_as_int(d0) >> 17) - LUT_BIAS;
        idx = idx < 0 ? 0 : (idx > LUT_N - 1 ? LUT_N - 1 : idx);
        int seg = __ldg(&gLut[idx]);
        while (__ldg(&gFineHi[seg]) < d0) seg++;
        if (tid < 5)      sSegRn[tid] = __ldg(&gRn[seg * 5 + tid]);
        else if (tid == 5) sSegHi = __ldg(&gFineHi[seg]);
        else if (tid == 6) sSegLo = (seg == 0) ? -__int_as_float(0x7f800000)
                                               : __ldg(&gFineHi[seg - 1]);
    }
    __syncthreads();

    const float segLo = sSegLo, segHi = sSegHi;

    float accR[3] = {0.f, 0.f, 0.f};
    float accI[3] = {0.f, 0.f, 0.f};

    // ---- main loop: batches of 4 pairs per warp ----
    for (int base = warp * 4; base < cntPad; base += 16) {
        float c1a[4], s1a[4], dv[4];
        float xmv[4][3];
        int   sg[4];

        #pragma unroll
        for (int p = 0; p < 4; p++) {
            const float2 ja = sJA[base + p];
            const int jv = (int)ja.x;
            const float aw = ja.y;
            const float2 rj = __ldg(&((const float2*)r)[b * NN + jv]);
            const float dx = ri.x - rj.x;
            const float dy = ri.y - rj.y;
            const float dd = fmaf(dx, dx, dy * dy);
            const float inv = rsqrtf(fmaxf(dd, 1e-30f));
            const float d  = dd * inv;
            dv[p]  = d;
            c1a[p] = dx * inv;
            s1a[p] = dy * inv;
            const float* __restrict__ xj = x + ((size_t)(b * NN + jv) * 3) * NC + lane;
            xmv[p][0] = __ldg(xj)          * aw;
            xmv[p][1] = __ldg(xj + NC)     * aw;
            xmv[p][2] = __ldg(xj + 2 * NC) * aw;

            if (d > segLo && d <= segHi) {
                sg[p] = -1;                         // cached fast path
            } else {
                int idx = (__float_as_int(d) >> 17) - LUT_BIAS;
                idx = idx < 0 ? 0 : (idx > LUT_N - 1 ? LUT_N - 1 : idx);
                int seg = __ldg(&gLut[idx]);
                while (__ldg(&gFineHi[seg]) < d) seg++;
                sg[p] = seg;
            }
        }

        #pragma unroll
        for (int p = 0; p < 4; p++) {
            const float d = dv[p];
            float4 q0, q1, q2, q3, q4;
            if (sg[p] < 0) {
                q0 = sSegRn[0]; q1 = sSegRn[1]; q2 = sSegRn[2];
                q3 = sSegRn[3]; q4 = sSegRn[4];
            } else {
                const float4* tp = &gRn[sg[p] * 5];
                q0 = __ldg(tp + 0); q1 = __ldg(tp + 1); q2 = __ldg(tp + 2);
                q3 = __ldg(tp + 3); q4 = __ldg(tp + 4);
            }
            float w[9];
            w[0] = fmaf(d, q2.y, q0.x);
            w[1] = fmaf(d, q2.z, q0.y);
            w[2] = fmaf(d, q2.w, q0.z);
            w[3] = fmaf(d, q3.x, q0.w);
            w[4] = fmaf(d, q3.y, q1.x);
            w[5] = fmaf(d, q3.z, q1.y);
            w[6] = fmaf(d, q3.w, q1.z);
            w[7] = fmaf(d, q4.x, q1.w);
            w[8] = fmaf(d, q4.y, q2.x);

            const float c1v = c1a[p], s1v = s1a[p];
            const float c2v = fmaf(2.f * c1v, c1v, -1.f);
            const float s2v = 2.f * s1v * c1v;
            const float cK[5] = { c2v,  c1v, 1.f, c1v, c2v };
            const float sK[5] = {-s2v, -s1v, 0.f, s1v, s2v };
            #pragma unroll
            for (int m = 0; m < 3; m++) {
                #pragma unroll
                for (int n = 0; n < 3; n++) {
                    const int k = n - m + 2;
                    const float u = w[m * 3 + n] * xmv[p][m];
                    accR[n] = fmaf(cK[k], u, accR[n]);
                    accI[n] = fmaf(sK[k], u, accI[n]);
                }
            }
        }
    }

    // ---- deterministic cross-warp reduction ----
    #pragma unroll
    for (int n = 0; n < 3; n++) {
        sPartR[warp][n * NC + lane] = accR[n];
        sPartI[warp][n * NC + lane] = accI[n];
    }
    __syncthreads();

    if (tid < 96) {
        const int n = tid / NC;
        const int c = tid % NC;
        const float sr  = sPartR[0][tid] + sPartR[1][tid] + sPartR[2][tid] + sPartR[3][tid];
        const float sim = sPartI[0][tid] + sPartI[1][tid] + sPartI[2][tid] + sPartI[3][tid];
        const float xs = x[((size_t)(b * NN + i) * 3 + n) * NC + c];
        const size_t baseR = ((((size_t)0 * NB + b) * NN + i) * 3 + n) * NC + c;
        const size_t baseI = ((((size_t)1 * NB + b) * NN + i) * 3 + n) * NC + c;
        out[baseR] = fmaf(sSi[n], xs, sr);   // self term: W_self = diag(si)
        out[baseI] = sim;
    }
}

extern "C" void kernel_launch(void* const* d_in, const int* in_sizes, int n_in,
                              void* d_out, int out_size) {
    const float* r   = (const float*)d_in[0];
    const float* x   = (const float*)d_in[1];
    const float* a   = (const float*)d_in[2];
    const float* W1  = (const float*)d_in[3];
    const float* b1  = (const float*)d_in[4];
    const float* g1  = (const float*)d_in[5];
    const float* be1 = (const float*)d_in[6];
    const float* m1  = (const float*)d_in[7];
    const float* v1  = (const float*)d_in[8];
    const float* W2  = (const float*)d_in[9];
    const float* b2  = (const float*)d_in[10];
    const float* g2  = (const float*)d_in[11];
    const float* be2 = (const float*)d_in[12];
    const float* m2  = (const float*)d_in[13];
    const float* v2  = (const float*)d_in[14];
    const float* W3  = (const float*)d_in[15];
    const float* b3  = (const float*)d_in[16];
    const float* si  = (const float*)d_in[17];
    float* out = (float*)d_out;

    prepB_kernel<<<65, 64>>>(W1, b1, g1, be1, m1, v1, W2, b2);
    prepD_kernel<<<65, 64>>>(W1, b1, g2, be2, m2, v2, W3, b3);
    prep2_kernel<<<(LUT_N + 255) / 256, 256>>>();
    e2conv_kernel<<<NB * NN, 128>>>(r, x, a, si, out);
}